// round 6
// baseline (speedup 1.0000x reference)
#include <cuda_runtime.h>
#include <cstdint>
#include <cfloat>
#include <math.h>

#define B_ 8
#define N_ 16384
#define NPOINT_ 1024
#define K_ 32
#define SAMPLE_NUM_ 10
#define SEL_ 7
#define SUBSET_ 29
#define RADIUS_ 0.2f

#define CLUSTER_ 8
#define SLICE_ (N_ / CLUSTER_)        // 2048 points per CTA
#define FPS_T_ 256
#define PPT_ (SLICE_ / FPS_T_)        // 8 points per thread

// FPS-selected center coordinates (B, NPOINT, 3)
__device__ float g_centers[B_ * NPOINT_ * 3];

struct Perms { unsigned char p[SAMPLE_NUM_][SUBSET_]; };

__device__ __forceinline__ unsigned smem_u32(const void* p) {
    unsigned a;
    asm("{ .reg .u64 t; cvta.to.shared.u64 t, %1; cvt.u32.u64 %0, t; }"
        : "=r"(a) : "l"(p));
    return a;
}

// ======================= Kernel A: cluster-parallel FPS (mbarrier exchange) ==========
// One 8-CTA cluster per batch. Points in registers. Candidate exchange:
// st.shared::cluster + mbarrier.arrive.release.cluster (count 8), parity
// ping-pong over 2 mbarriers -> no barrier.cluster in the loop.
__global__ __launch_bounds__(FPS_T_) __cluster_dims__(CLUSTER_, 1, 1)
void fps_cluster_kernel(const float* __restrict__ xyz)
{
    __shared__ float ox[SLICE_], oy[SLICE_], oz[SLICE_];
    __shared__ unsigned long long warr[FPS_T_ / 32];
    __shared__ unsigned long long skey[2][CLUSTER_];
    __shared__ float scx[2][CLUSTER_], scy[2][CLUSTER_], scz[2][CLUSTER_];
    __shared__ __align__(8) unsigned long long mbar[2];

    const int t = threadIdx.x;
    unsigned rank;
    asm("mov.u32 %0, %%cluster_ctarank;" : "=r"(rank));
    const int b = blockIdx.x >> 3;
    const int base = (int)rank * SLICE_;
    const float* X = xyz + (size_t)b * N_ * 3;

    if (t == 0) {
        unsigned a0 = smem_u32(&mbar[0]);
        unsigned a1 = smem_u32(&mbar[1]);
        asm volatile("mbarrier.init.shared.b64 [%0], %1;" :: "r"(a0), "r"(CLUSTER_) : "memory");
        asm volatile("mbarrier.init.shared.b64 [%0], %1;" :: "r"(a1), "r"(CLUSTER_) : "memory");
    }

    float px[PPT_], py[PPT_], pz[PPT_], dd[PPT_];
#pragma unroll
    for (int k = 0; k < PPT_; k++) {
        int l = (k << 8) + t;          // local index in slice
        int n = base + l;
        float x = X[n * 3 + 0], y = X[n * 3 + 1], z = X[n * 3 + 2];
        px[k] = x; py[k] = y; pz[k] = z;
        ox[l] = x; oy[l] = y; oz[l] = z;
        dd[k] = 1e10f;
    }
    __syncthreads();
    // all mbarriers initialized cluster-wide before any remote arrive
    asm volatile("barrier.cluster.arrive.aligned;" ::: "memory");
    asm volatile("barrier.cluster.wait.aligned;" ::: "memory");

    // initial centroid = point 0 (reference starts farthest=0)
    float cx = X[0], cy = X[1], cz = X[2];

    float* outc = g_centers + (size_t)b * NPOINT_ * 3;

    for (int s = 0; s < NPOINT_; s++) {
        if (rank == 0 && t == 0) {
            outc[s * 3 + 0] = cx; outc[s * 3 + 1] = cy; outc[s * 3 + 2] = cz;
        }
        const int par = s & 1;
        const unsigned ph = (unsigned)((s >> 1) & 1);

        unsigned long long best = 0ull;
#pragma unroll
        for (int k = 0; k < PPT_; k++) {
            int n = base + (k << 8) + t;
            // match XLA: ((dx*dx + dy*dy) + dz*dz), each op rounded, no FMA
            float dx = __fsub_rn(px[k], cx);
            float dy = __fsub_rn(py[k], cy);
            float dz = __fsub_rn(pz[k], cz);
            float d  = __fadd_rn(__fadd_rn(__fmul_rn(dx, dx), __fmul_rn(dy, dy)),
                                 __fmul_rn(dz, dz));
            float nd = fminf(dd[k], d);
            dd[k] = nd;
            unsigned long long pk =
                ((unsigned long long)__float_as_uint(nd) << 32) | (unsigned)(~n);
            best = (pk > best) ? pk : best;
        }
#pragma unroll
        for (int off = 16; off > 0; off >>= 1) {
            unsigned long long o = __shfl_xor_sync(0xffffffffu, best, off);
            best = (o > best) ? o : best;
        }
        if ((t & 31) == 0) warr[t >> 5] = best;
        __syncthreads();

        // threads 0..7: CTA-best then broadcast candidate to cluster CTA t
        if (t < CLUSTER_) {
            unsigned long long bb = warr[0];
#pragma unroll
            for (int w = 1; w < FPS_T_ / 32; w++) {
                unsigned long long v = warr[w];
                bb = (v > bb) ? v : bb;
            }
            int g = (int)(~(unsigned)(bb & 0xffffffffu));
            int l = g - base;
            float wx = ox[l], wy = oy[l], wz = oz[l];
            unsigned a_key = smem_u32(&skey[par][rank]);
            unsigned a_cx  = smem_u32(&scx[par][rank]);
            unsigned a_cy  = smem_u32(&scy[par][rank]);
            unsigned a_cz  = smem_u32(&scz[par][rank]);
            unsigned a_mb  = smem_u32(&mbar[par]);
            unsigned r_key, r_cx, r_cy, r_cz, r_mb;
            asm("mapa.shared::cluster.u32 %0, %1, %2;" : "=r"(r_key) : "r"(a_key), "r"(t));
            asm("mapa.shared::cluster.u32 %0, %1, %2;" : "=r"(r_cx)  : "r"(a_cx),  "r"(t));
            asm("mapa.shared::cluster.u32 %0, %1, %2;" : "=r"(r_cy)  : "r"(a_cy),  "r"(t));
            asm("mapa.shared::cluster.u32 %0, %1, %2;" : "=r"(r_cz)  : "r"(a_cz),  "r"(t));
            asm("mapa.shared::cluster.u32 %0, %1, %2;" : "=r"(r_mb)  : "r"(a_mb),  "r"(t));
            asm volatile("st.shared::cluster.b64 [%0], %1;" :: "r"(r_key), "l"(bb) : "memory");
            asm volatile("st.shared::cluster.b32 [%0], %1;" :: "r"(r_cx), "r"(__float_as_uint(wx)) : "memory");
            asm volatile("st.shared::cluster.b32 [%0], %1;" :: "r"(r_cy), "r"(__float_as_uint(wy)) : "memory");
            asm volatile("st.shared::cluster.b32 [%0], %1;" :: "r"(r_cz), "r"(__float_as_uint(wz)) : "memory");
            asm volatile("mbarrier.arrive.release.cluster.shared::cluster.b64 _, [%0];"
                         :: "r"(r_mb) : "memory");
        }

        // all threads: wait for 8 arrivals on own mbar[par] (acquire, cluster scope)
        {
            unsigned a_mb = smem_u32(&mbar[par]);
            unsigned done;
            asm volatile(
                "{\n\t"
                ".reg .pred p;\n\t"
                "mbarrier.try_wait.parity.acquire.cluster.shared::cta.b64 p, [%1], %2;\n\t"
                "selp.b32 %0, 1, 0, p;\n\t"
                "}"
                : "=r"(done) : "r"(a_mb), "r"(ph) : "memory");
            if (!done) {
                asm volatile(
                    "{\n\t"
                    ".reg .pred P1;\n\t"
                    "W_%=:\n\t"
                    "mbarrier.try_wait.parity.acquire.cluster.shared::cta.b64 P1, [%0], %1, 0x989680;\n\t"
                    "@P1 bra.uni D_%=;\n\t"
                    "bra.uni W_%=;\n\t"
                    "D_%=:\n\t"
                    "}"
                    :: "r"(a_mb), "r"(ph) : "memory");
            }
        }

        // winner among the 8 slots (broadcast LDS)
        unsigned long long w0 = skey[par][0];
        int wi = 0;
#pragma unroll
        for (int r = 1; r < CLUSTER_; r++) {
            unsigned long long v = skey[par][r];
            if (v > w0) { w0 = v; wi = r; }
        }
        cx = scx[par][wi]; cy = scy[par][wi]; cz = scz[par][wi];
    }
}

// ======================= Kernel B: KNN + robust centroid + features =======================
// One block per center (8192 blocks, 256 threads). No big smem key array ->
// 4 CTAs/SM. Per-thread min1/min2 cache; O(1) owner update; rare fallback
// recomputes its 64 points from global excluding removed indices.
__global__ __launch_bounds__(256, 4) void knn_feat_kernel(const float* __restrict__ xyz,
                                                          float* __restrict__ out,
                                                          Perms perms)
{
    __shared__ unsigned long long warr2[2][8];
    __shared__ int nb[K_];
    __shared__ float gx[K_], gy[K_], gz[K_];
    __shared__ float cdx[SAMPLE_NUM_], cdy[SAMPLE_NUM_], cdz[SAMPLE_NUM_];

    const int bs = blockIdx.x;           // b * NPOINT + s
    const int b = bs >> 10;
    const int t = threadIdx.x;
    const float* X = xyz + (size_t)b * N_ * 3;

    const float cx = g_centers[bs * 3 + 0];
    const float cy = g_centers[bs * 3 + 1];
    const float cz = g_centers[bs * 3 + 2];
    const float cc = __fadd_rn(__fadd_rn(__fmul_rn(cx, cx), __fmul_rn(cy, cy)),
                               __fmul_rn(cz, cz));

    unsigned long long m1 = 0xFFFFFFFFFFFFFFFFull, m2 = 0xFFFFFFFFFFFFFFFFull;
#pragma unroll 8
    for (int k = 0; k < 64; k++) {
        int n = t + (k << 8);
        float x = __ldg(&X[n * 3 + 0]), y = __ldg(&X[n * 3 + 1]), z = __ldg(&X[n * 3 + 2]);
        float xx = __fadd_rn(__fadd_rn(__fmul_rn(x, x), __fmul_rn(y, y)),
                             __fmul_rn(z, z));
        float dt = __fadd_rn(__fadd_rn(__fmul_rn(cx, x), __fmul_rn(cy, y)),
                             __fmul_rn(cz, z));
        // match reference: (cc + xx) - 2*dot
        float d2 = __fsub_rn(__fadd_rn(cc, xx), __fmul_rn(2.0f, dt));
        unsigned fb = __float_as_uint(d2);
        fb = (fb & 0x80000000u) ? ~fb : (fb | 0x80000000u);   // monotone map
        unsigned long long pk = ((unsigned long long)fb << 32) | (unsigned)n;
        if (pk < m1) { m2 = m1; m1 = pk; }
        else if (pk < m2) { m2 = pk; }
    }
    unsigned long long best = m1;
    int rem = 0;

    // ---- select K_ nearest, ascending d2, ties -> lower index (lax.top_k order) ----
    for (int j = 0; j < K_; j++) {
        const int par = j & 1;
        unsigned long long v = best;
#pragma unroll
        for (int off = 16; off > 0; off >>= 1) {
            unsigned long long o = __shfl_xor_sync(0xffffffffu, v, off);
            v = (o < v) ? o : v;
        }
        if ((t & 31) == 0) warr2[par][t >> 5] = v;
        __syncthreads();

        unsigned long long m = warr2[par][0];
#pragma unroll
        for (int w = 1; w < 8; w++) {
            unsigned long long u = warr2[par][w];
            m = (u < m) ? u : m;
        }
        int sel = (int)(unsigned)(m & 0xffffffffu);
        if (t == 0) nb[j] = sel;

        if ((sel & 255) == t) {           // owner: O(1) update, rare global rescan
            rem++;
            if (rem == 1) {
                best = m2;
            } else {
                unsigned long long nb2 = 0xFFFFFFFFFFFFFFFFull;
                for (int k = 0; k < 64; k++) {
                    int n = t + (k << 8);
                    bool rm = (n == sel);
                    for (int jj = 0; jj < j; jj++) rm |= (nb[jj] == n);
                    if (rm) continue;
                    float x = __ldg(&X[n * 3 + 0]), y = __ldg(&X[n * 3 + 1]), z = __ldg(&X[n * 3 + 2]);
                    float xx = __fadd_rn(__fadd_rn(__fmul_rn(x, x), __fmul_rn(y, y)),
                                         __fmul_rn(z, z));
                    float dt = __fadd_rn(__fadd_rn(__fmul_rn(cx, x), __fmul_rn(cy, y)),
                                         __fmul_rn(cz, z));
                    float d2 = __fsub_rn(__fadd_rn(cc, xx), __fmul_rn(2.0f, dt));
                    unsigned fb = __float_as_uint(d2);
                    fb = (fb & 0x80000000u) ? ~fb : (fb | 0x80000000u);
                    unsigned long long pk = ((unsigned long long)fb << 32) | (unsigned)n;
                    nb2 = (pk < nb2) ? pk : nb2;
                }
                best = nb2;
            }
        }
    }
    __syncthreads();

    // ---- gather the 32 neighbors (in selection order) ----
    if (t < K_) {
        int n = nb[t];
        gx[t] = X[n * 3 + 0];
        gy[t] = X[n * 3 + 1];
        gz[t] = X[n * 3 + 2];
    }
    __syncthreads();

    // ---- 10 candidate centroids: mean over fixed 29-element permutation subsets ----
    if (t < SAMPLE_NUM_) {
        float ax = 0.f, ay = 0.f, az = 0.f;
        for (int j = 0; j < SUBSET_; j++) {
            int p = perms.p[t][j];
            ax += gx[p]; ay += gy[p]; az += gz[p];
        }
        cdx[t] = ax / (float)SUBSET_;
        cdy[t] = ay / (float)SUBSET_;
        cdz[t] = az / (float)SUBSET_;
    }
    __syncthreads();

    // ---- candidate selection (7 most central of 10) + features ----
    if (t == 0) {
        float sq[SAMPLE_NUM_], ps[SAMPLE_NUM_];
        for (int j = 0; j < SAMPLE_NUM_; j++)
            sq[j] = cdx[j] * cdx[j] + cdy[j] * cdy[j] + cdz[j] * cdz[j];
        for (int j = 0; j < SAMPLE_NUM_; j++) {
            float acc = 0.f;
            for (int k2 = 0; k2 < SAMPLE_NUM_; k2++) {
                float dt = cdx[j] * cdx[k2] + cdy[j] * cdy[k2] + cdz[j] * cdz[k2];
                acc += sq[j] + sq[k2] - 2.0f * dt;
            }
            ps[j] = acc;
        }
        bool used[SAMPLE_NUM_];
        for (int j = 0; j < SAMPLE_NUM_; j++) used[j] = false;
        float mx = 0.f, my = 0.f, mz = 0.f;
        for (int r = 0; r < SEL_; r++) {
            int bsel = 0; float bv = FLT_MAX;
            for (int k2 = 0; k2 < SAMPLE_NUM_; k2++)
                if (!used[k2] && ps[k2] < bv) { bv = ps[k2]; bsel = k2; }
            used[bsel] = true;
            mx += cdx[bsel]; my += cdy[bsel]; mz += cdz[bsel];
        }
        mx /= (float)SEL_; my /= (float)SEL_; mz /= (float)SEL_;

        float ref_norm = sqrtf(cx * cx + cy * cy + cz * cz);
        float den = ref_norm + 1e-4f;
        float ux = cx / den, uy = cy / den, uz = cz / den;
        float ix = RADIUS_ * ux + cx, iy = RADIUS_ * uy + cy, iz = RADIUS_ * uz + cz;

        float crx = cx - mx, cry = cy - my, crz = cz - mz;
        float crd = sqrtf(crx * crx + cry * cry + crz * crz);
        float cvx = ix - mx, cvy = iy - my, cvz = iz - mz;
        float cid = sqrtf(cvx * cvx + cvy * cvy + cvz * cvz);
        float dot = crx * cvx + cry * cvy + crz * cvz;
        float ang_rci = dot / (crd * cid + 1e-6f);

        float irx = cx - ix, iry = cy - iy, irz = cz - iz;
        float icx = mx - ix, icy = my - iy, icz = mz - iz;
        float dot2 = irx * icx + iry * icy + irz * icz;
        float ang_ric = dot2 / (RADIUS_ * cid + 1e-6f);

        float* o = out + (size_t)bs * 5;
        o[0] = ref_norm; o[1] = crd; o[2] = cid; o[3] = ang_rci; o[4] = ang_ric;
    }
}

// ======================= Host: threefry-2x32 (JAX partitionable PRNG) =======================
static inline uint32_t rotl32_(uint32_t x, int r) { return (x << r) | (x >> (32 - r)); }

static void tf2x32_(uint32_t k0, uint32_t k1, uint32_t x0, uint32_t x1,
                    uint32_t& o0, uint32_t& o1)
{
    static const int R0[4] = {13, 15, 26, 6};
    static const int R1[4] = {17, 29, 16, 24};
    uint32_t ks[3] = {k0, k1, k0 ^ k1 ^ 0x1BD11BDAu};
    x0 += ks[0]; x1 += ks[1];
    for (int i = 0; i < 5; i++) {
        const int* R = (i & 1) ? R1 : R0;
        for (int j = 0; j < 4; j++) { x0 += x1; x1 = rotl32_(x1, R[j]); x1 ^= x0; }
        x0 += ks[(i + 1) % 3];
        x1 += ks[(i + 2) % 3] + (uint32_t)(i + 1);
    }
    o0 = x0; o1 = x1;
}

// jax.random.permutation(fold_in(key(42), i), 32)[:29], threefry partitionable mode.
static void make_perms(unsigned char p[SAMPLE_NUM_][SUBSET_])
{
    for (int i = 0; i < SAMPLE_NUM_; i++) {
        uint32_t k0, k1, s0, s1;
        tf2x32_(0u, 42u, 0u, (uint32_t)i, k0, k1);     // fold_in
        tf2x32_(k0, k1, 0u, 1u, s0, s1);               // split -> subkey (index 1)
        uint32_t bits[K_];
        for (int j = 0; j < K_; j++) {
            uint32_t hi, lo;
            tf2x32_(s0, s1, 0u, (uint32_t)j, hi, lo);
            bits[j] = hi ^ lo;                         // 32-bit path XORs both words
        }
        int idx[K_];
        for (int j = 0; j < K_; j++) idx[j] = j;
        for (int a = 1; a < K_; a++) {                 // stable insertion sort
            uint32_t bv = bits[a]; int iv = idx[a]; int c = a - 1;
            while (c >= 0 && bits[c] > bv) {
                bits[c + 1] = bits[c]; idx[c + 1] = idx[c]; c--;
            }
            bits[c + 1] = bv; idx[c + 1] = iv;
        }
        for (int j = 0; j < SUBSET_; j++) p[i][j] = (unsigned char)idx[j];
    }
}

extern "C" void kernel_launch(void* const* d_in, const int* in_sizes, int n_in,
                              void* d_out, int out_size)
{
    (void)in_sizes; (void)n_in; (void)out_size;
    const float* xyz = (const float*)d_in[0];
    float* out = (float*)d_out;

    Perms perms;
    make_perms(perms.p);   // deterministic, cheap, every call

    fps_cluster_kernel<<<B_ * CLUSTER_, FPS_T_>>>(xyz);
    knn_feat_kernel<<<B_ * NPOINT_, 256>>>(xyz, out, perms);
}

// round 7
// speedup vs baseline: 1.0487x; 1.0487x over previous
#include <cuda_runtime.h>
#include <cstdint>
#include <cfloat>
#include <math.h>

#define B_ 8
#define N_ 16384
#define NPOINT_ 1024
#define K_ 32
#define SAMPLE_NUM_ 10
#define SEL_ 7
#define SUBSET_ 29
#define RADIUS_ 0.2f

#define CLUSTER_ 8
#define SLICE_ (N_ / CLUSTER_)        // 2048 points per CTA
#define FPS_T_ 256
#define PPT_ (SLICE_ / FPS_T_)        // 8 points per thread

// FPS-selected center coordinates (B, NPOINT, 3)
__device__ float g_centers[B_ * NPOINT_ * 3];

struct Perms { unsigned char p[SAMPLE_NUM_][SUBSET_]; };

__device__ __forceinline__ unsigned smem_u32(const void* p) {
    unsigned a;
    asm("{ .reg .u64 t; cvta.to.shared.u64 t, %1; cvt.u32.u64 %0, t; }"
        : "=r"(a) : "l"(p));
    return a;
}

// ======================= Kernel A: cluster-parallel FPS (R4 version) =======================
// One 8-CTA cluster per batch. Each CTA owns a 2048-pt slice in registers;
// per-iteration candidate exchange via DSMEM slots + one cluster barrier
// (parity double-buffered). Packed (dist_bits<<32 | ~idx) max reproduces
// jnp.argmax first-index tie semantics exactly.
__global__ __launch_bounds__(FPS_T_) __cluster_dims__(CLUSTER_, 1, 1)
void fps_cluster_kernel(const float* __restrict__ xyz)
{
    __shared__ float ox[SLICE_], oy[SLICE_], oz[SLICE_];
    __shared__ unsigned long long warr[FPS_T_ / 32];
    __shared__ unsigned long long skey[2][CLUSTER_];
    __shared__ float scx[2][CLUSTER_], scy[2][CLUSTER_], scz[2][CLUSTER_];

    const int t = threadIdx.x;
    unsigned rank;
    asm("mov.u32 %0, %%cluster_ctarank;" : "=r"(rank));
    const int b = blockIdx.x >> 3;
    const int base = (int)rank * SLICE_;
    const float* X = xyz + (size_t)b * N_ * 3;

    float px[PPT_], py[PPT_], pz[PPT_], dd[PPT_];
#pragma unroll
    for (int k = 0; k < PPT_; k++) {
        int l = (k << 8) + t;          // local index in slice
        int n = base + l;
        float x = X[n * 3 + 0], y = X[n * 3 + 1], z = X[n * 3 + 2];
        px[k] = x; py[k] = y; pz[k] = z;
        ox[l] = x; oy[l] = y; oz[l] = z;
        dd[k] = 1e10f;
    }
    __syncthreads();

    // initial centroid = point 0 (reference starts farthest=0)
    float cx = X[0], cy = X[1], cz = X[2];

    float* outc = g_centers + (size_t)b * NPOINT_ * 3;

    for (int s = 0; s < NPOINT_; s++) {
        if (rank == 0 && t == 0) {
            outc[s * 3 + 0] = cx; outc[s * 3 + 1] = cy; outc[s * 3 + 2] = cz;
        }
        const int par = s & 1;

        unsigned long long best = 0ull;
#pragma unroll
        for (int k = 0; k < PPT_; k++) {
            int n = base + (k << 8) + t;
            // match XLA: ((dx*dx + dy*dy) + dz*dz), each op rounded, no FMA
            float dx = __fsub_rn(px[k], cx);
            float dy = __fsub_rn(py[k], cy);
            float dz = __fsub_rn(pz[k], cz);
            float d  = __fadd_rn(__fadd_rn(__fmul_rn(dx, dx), __fmul_rn(dy, dy)),
                                 __fmul_rn(dz, dz));
            float nd = fminf(dd[k], d);
            dd[k] = nd;
            unsigned long long pk =
                ((unsigned long long)__float_as_uint(nd) << 32) | (unsigned)(~n);
            best = (pk > best) ? pk : best;
        }
        // warp xor-reduce: every lane ends with warp max
#pragma unroll
        for (int off = 16; off > 0; off >>= 1) {
            unsigned long long o = __shfl_xor_sync(0xffffffffu, best, off);
            best = (o > best) ? o : best;
        }
        if ((t & 31) == 0) warr[t >> 5] = best;
        __syncthreads();

        // all threads compute CTA-best (broadcast LDS reads)
        unsigned long long bb = warr[0];
#pragma unroll
        for (int w = 1; w < FPS_T_ / 32; w++) {
            unsigned long long v = warr[w];
            bb = (v > bb) ? v : bb;
        }

        // threads 0..7: send this CTA's candidate to cluster CTA t's slot[rank][par]
        if (t < CLUSTER_) {
            int g = (int)(~(unsigned)(bb & 0xffffffffu));
            int l = g - base;
            float wx = ox[l], wy = oy[l], wz = oz[l];
            unsigned a_key = smem_u32(&skey[par][rank]);
            unsigned a_cx  = smem_u32(&scx[par][rank]);
            unsigned a_cy  = smem_u32(&scy[par][rank]);
            unsigned a_cz  = smem_u32(&scz[par][rank]);
            unsigned r_key, r_cx, r_cy, r_cz;
            asm("mapa.shared::cluster.u32 %0, %1, %2;" : "=r"(r_key) : "r"(a_key), "r"(t));
            asm("mapa.shared::cluster.u32 %0, %1, %2;" : "=r"(r_cx)  : "r"(a_cx),  "r"(t));
            asm("mapa.shared::cluster.u32 %0, %1, %2;" : "=r"(r_cy)  : "r"(a_cy),  "r"(t));
            asm("mapa.shared::cluster.u32 %0, %1, %2;" : "=r"(r_cz)  : "r"(a_cz),  "r"(t));
            asm volatile("st.shared::cluster.b64 [%0], %1;" :: "r"(r_key), "l"(bb) : "memory");
            asm volatile("st.shared::cluster.b32 [%0], %1;" :: "r"(r_cx), "r"(__float_as_uint(wx)) : "memory");
            asm volatile("st.shared::cluster.b32 [%0], %1;" :: "r"(r_cy), "r"(__float_as_uint(wy)) : "memory");
            asm volatile("st.shared::cluster.b32 [%0], %1;" :: "r"(r_cz), "r"(__float_as_uint(wz)) : "memory");
        }

        // one cluster barrier per iteration (release orders the DSMEM stores)
        asm volatile("barrier.cluster.arrive.aligned;" ::: "memory");
        asm volatile("barrier.cluster.wait.aligned;" ::: "memory");

        // every thread: winner among the 8 slots (broadcast LDS, no extra barrier;
        // slot reuse is safe via parity + the interleaving cluster barrier)
        unsigned long long w0 = skey[par][0];
        int wi = 0;
#pragma unroll
        for (int r = 1; r < CLUSTER_; r++) {
            unsigned long long v = skey[par][r];
            if (v > w0) { w0 = v; wi = r; }
        }
        cx = scx[par][wi]; cy = scy[par][wi]; cz = scz[par][wi];
    }
}

// ======================= Kernel B: KNN + robust centroid + features =======================
// One block per center (8192 blocks, 256 threads). Float min1/min2 scan
// (strict < == first-index tie semantics; d2 is never -0.0), packed-u64
// block reduce per round, O(1) owner update with rare global rescan.
__global__ __launch_bounds__(256, 4) void knn_feat_kernel(const float* __restrict__ xyz,
                                                          float* __restrict__ out,
                                                          Perms perms)
{
    __shared__ unsigned long long warr2[2][8];
    __shared__ int nb[K_];
    __shared__ float gx[K_], gy[K_], gz[K_];
    __shared__ float cdx[SAMPLE_NUM_], cdy[SAMPLE_NUM_], cdz[SAMPLE_NUM_];

    const int bs = blockIdx.x;           // b * NPOINT + s
    const int b = bs >> 10;
    const int t = threadIdx.x;
    const float* X = xyz + (size_t)b * N_ * 3;

    const float cx = g_centers[bs * 3 + 0];
    const float cy = g_centers[bs * 3 + 1];
    const float cz = g_centers[bs * 3 + 2];
    const float cc = __fadd_rn(__fadd_rn(__fmul_rn(cx, cx), __fmul_rn(cy, cy)),
                               __fmul_rn(cz, cz));

    // float min1/min2 with index tracking (strict < keeps first index on ties)
    float v1 = FLT_MAX, v2 = FLT_MAX;
    int i1 = 0, i2 = 0;
#pragma unroll 8
    for (int k = 0; k < 64; k++) {
        int n = t + (k << 8);
        float x = __ldg(&X[n * 3 + 0]), y = __ldg(&X[n * 3 + 1]), z = __ldg(&X[n * 3 + 2]);
        float xx = __fadd_rn(__fadd_rn(__fmul_rn(x, x), __fmul_rn(y, y)),
                             __fmul_rn(z, z));
        float dt = __fadd_rn(__fadd_rn(__fmul_rn(cx, x), __fmul_rn(cy, y)),
                             __fmul_rn(cz, z));
        // match reference: (cc + xx) - 2*dot
        float d2 = __fsub_rn(__fadd_rn(cc, xx), __fmul_rn(2.0f, dt));
        if (d2 < v1)      { v2 = v1; i2 = i1; v1 = d2; i1 = n; }
        else if (d2 < v2) { v2 = d2; i2 = n; }
    }

    // pack to monotone u64 keys once (d2 never -0.0 -> order identical to float cmp)
    auto pack = [](float v, int n) -> unsigned long long {
        unsigned fb = __float_as_uint(v);
        fb = (fb & 0x80000000u) ? ~fb : (fb | 0x80000000u);
        return ((unsigned long long)fb << 32) | (unsigned)n;
    };
    unsigned long long best = pack(v1, i1);
    unsigned long long m2k  = pack(v2, i2);
    int rem = 0;

    // ---- select K_ nearest, ascending d2, ties -> lower index (lax.top_k order) ----
    for (int j = 0; j < K_; j++) {
        const int par = j & 1;
        unsigned long long v = best;
#pragma unroll
        for (int off = 16; off > 0; off >>= 1) {
            unsigned long long o = __shfl_xor_sync(0xffffffffu, v, off);
            v = (o < v) ? o : v;
        }
        if ((t & 31) == 0) warr2[par][t >> 5] = v;
        __syncthreads();

        unsigned long long m = warr2[par][0];
#pragma unroll
        for (int w = 1; w < 8; w++) {
            unsigned long long u = warr2[par][w];
            m = (u < m) ? u : m;
        }
        int sel = (int)(unsigned)(m & 0xffffffffu);
        if (t == 0) nb[j] = sel;

        if ((sel & 255) == t) {           // owner: O(1) update, rare global rescan
            rem++;
            if (rem == 1) {
                best = m2k;
            } else {
                unsigned long long nb2 = 0xFFFFFFFFFFFFFFFFull;
                for (int k = 0; k < 64; k++) {
                    int n = t + (k << 8);
                    bool rm = (n == sel);
                    for (int jj = 0; jj < j; jj++) rm |= (nb[jj] == n);
                    if (rm) continue;
                    float x = __ldg(&X[n * 3 + 0]), y = __ldg(&X[n * 3 + 1]), z = __ldg(&X[n * 3 + 2]);
                    float xx = __fadd_rn(__fadd_rn(__fmul_rn(x, x), __fmul_rn(y, y)),
                                         __fmul_rn(z, z));
                    float dt = __fadd_rn(__fadd_rn(__fmul_rn(cx, x), __fmul_rn(cy, y)),
                                         __fmul_rn(cz, z));
                    float d2 = __fsub_rn(__fadd_rn(cc, xx), __fmul_rn(2.0f, dt));
                    unsigned fb = __float_as_uint(d2);
                    fb = (fb & 0x80000000u) ? ~fb : (fb | 0x80000000u);
                    unsigned long long pk = ((unsigned long long)fb << 32) | (unsigned)n;
                    nb2 = (pk < nb2) ? pk : nb2;
                }
                best = nb2;
            }
        }
    }
    __syncthreads();

    // ---- gather the 32 neighbors (in selection order) ----
    if (t < K_) {
        int n = nb[t];
        gx[t] = X[n * 3 + 0];
        gy[t] = X[n * 3 + 1];
        gz[t] = X[n * 3 + 2];
    }
    __syncthreads();

    // ---- 10 candidate centroids: mean over fixed 29-element permutation subsets ----
    if (t < SAMPLE_NUM_) {
        float ax = 0.f, ay = 0.f, az = 0.f;
        for (int j = 0; j < SUBSET_; j++) {
            int p = perms.p[t][j];
            ax += gx[p]; ay += gy[p]; az += gz[p];
        }
        cdx[t] = ax / (float)SUBSET_;
        cdy[t] = ay / (float)SUBSET_;
        cdz[t] = az / (float)SUBSET_;
    }
    __syncthreads();

    // ---- candidate selection (7 most central of 10) + features ----
    if (t == 0) {
        float sq[SAMPLE_NUM_], ps[SAMPLE_NUM_];
        for (int j = 0; j < SAMPLE_NUM_; j++)
            sq[j] = cdx[j] * cdx[j] + cdy[j] * cdy[j] + cdz[j] * cdz[j];
        for (int j = 0; j < SAMPLE_NUM_; j++) {
            float acc = 0.f;
            for (int k2 = 0; k2 < SAMPLE_NUM_; k2++) {
                float dt = cdx[j] * cdx[k2] + cdy[j] * cdy[k2] + cdz[j] * cdz[k2];
                acc += sq[j] + sq[k2] - 2.0f * dt;
            }
            ps[j] = acc;
        }
        bool used[SAMPLE_NUM_];
        for (int j = 0; j < SAMPLE_NUM_; j++) used[j] = false;
        float mx = 0.f, my = 0.f, mz = 0.f;
        for (int r = 0; r < SEL_; r++) {
            int bsel = 0; float bv = FLT_MAX;
            for (int k2 = 0; k2 < SAMPLE_NUM_; k2++)
                if (!used[k2] && ps[k2] < bv) { bv = ps[k2]; bsel = k2; }
            used[bsel] = true;
            mx += cdx[bsel]; my += cdy[bsel]; mz += cdz[bsel];
        }
        mx /= (float)SEL_; my /= (float)SEL_; mz /= (float)SEL_;

        float ref_norm = sqrtf(cx * cx + cy * cy + cz * cz);
        float den = ref_norm + 1e-4f;
        float ux = cx / den, uy = cy / den, uz = cz / den;
        float ix = RADIUS_ * ux + cx, iy = RADIUS_ * uy + cy, iz = RADIUS_ * uz + cz;

        float crx = cx - mx, cry = cy - my, crz = cz - mz;
        float crd = sqrtf(crx * crx + cry * cry + crz * crz);
        float cvx = ix - mx, cvy = iy - my, cvz = iz - mz;
        float cid = sqrtf(cvx * cvx + cvy * cvy + cvz * cvz);
        float dot = crx * cvx + cry * cvy + crz * cvz;
        float ang_rci = dot / (crd * cid + 1e-6f);

        float irx = cx - ix, iry = cy - iy, irz = cz - iz;
        float icx = mx - ix, icy = my - iy, icz = mz - iz;
        float dot2 = irx * icx + iry * icy + irz * icz;
        float ang_ric = dot2 / (RADIUS_ * cid + 1e-6f);

        float* o = out + (size_t)bs * 5;
        o[0] = ref_norm; o[1] = crd; o[2] = cid; o[3] = ang_rci; o[4] = ang_ric;
    }
}

// ======================= Host: threefry-2x32 (JAX partitionable PRNG) =======================
static inline uint32_t rotl32_(uint32_t x, int r) { return (x << r) | (x >> (32 - r)); }

static void tf2x32_(uint32_t k0, uint32_t k1, uint32_t x0, uint32_t x1,
                    uint32_t& o0, uint32_t& o1)
{
    static const int R0[4] = {13, 15, 26, 6};
    static const int R1[4] = {17, 29, 16, 24};
    uint32_t ks[3] = {k0, k1, k0 ^ k1 ^ 0x1BD11BDAu};
    x0 += ks[0]; x1 += ks[1];
    for (int i = 0; i < 5; i++) {
        const int* R = (i & 1) ? R1 : R0;
        for (int j = 0; j < 4; j++) { x0 += x1; x1 = rotl32_(x1, R[j]); x1 ^= x0; }
        x0 += ks[(i + 1) % 3];
        x1 += ks[(i + 2) % 3] + (uint32_t)(i + 1);
    }
    o0 = x0; o1 = x1;
}

// jax.random.permutation(fold_in(key(42), i), 32)[:29], threefry partitionable mode.
static void make_perms(unsigned char p[SAMPLE_NUM_][SUBSET_])
{
    for (int i = 0; i < SAMPLE_NUM_; i++) {
        uint32_t k0, k1, s0, s1;
        tf2x32_(0u, 42u, 0u, (uint32_t)i, k0, k1);     // fold_in
        tf2x32_(k0, k1, 0u, 1u, s0, s1);               // split -> subkey (index 1)
        uint32_t bits[K_];
        for (int j = 0; j < K_; j++) {
            uint32_t hi, lo;
            tf2x32_(s0, s1, 0u, (uint32_t)j, hi, lo);
            bits[j] = hi ^ lo;                         // 32-bit path XORs both words
        }
        int idx[K_];
        for (int j = 0; j < K_; j++) idx[j] = j;
        for (int a = 1; a < K_; a++) {                 // stable insertion sort
            uint32_t bv = bits[a]; int iv = idx[a]; int c = a - 1;
            while (c >= 0 && bits[c] > bv) {
                bits[c + 1] = bits[c]; idx[c + 1] = idx[c]; c--;
            }
            bits[c + 1] = bv; idx[c + 1] = iv;
        }
        for (int j = 0; j < SUBSET_; j++) p[i][j] = (unsigned char)idx[j];
    }
}

extern "C" void kernel_launch(void* const* d_in, const int* in_sizes, int n_in,
                              void* d_out, int out_size)
{
    (void)in_sizes; (void)n_in; (void)out_size;
    const float* xyz = (const float*)d_in[0];
    float* out = (float*)d_out;

    Perms perms;
    make_perms(perms.p);   // deterministic, cheap, every call

    fps_cluster_kernel<<<B_ * CLUSTER_, FPS_T_>>>(xyz);
    knn_feat_kernel<<<B_ * NPOINT_, 256>>>(xyz, out, perms);
}

// round 8
// speedup vs baseline: 1.8553x; 1.7690x over previous
#include <cuda_runtime.h>
#include <cstdint>
#include <cfloat>
#include <math.h>

#define B_ 8
#define N_ 16384
#define NPOINT_ 1024
#define K_ 32
#define SAMPLE_NUM_ 10
#define SEL_ 7
#define SUBSET_ 29
#define RADIUS_ 0.2f

#define CLUSTER_ 8
#define SLICE_ (N_ / CLUSTER_)        // 2048 points per CTA
#define FPS_T_ 256
#define PPT_ (SLICE_ / FPS_T_)        // 8 points per thread

// FPS-selected center coordinates (B, NPOINT, 3)
__device__ float g_centers[B_ * NPOINT_ * 3];
// Packed points: (x, y, z, xx) with xx = ((x*x+y*y)+z*z) reference-rounded
__device__ float4 g_pts[B_ * N_];

struct Perms { unsigned char p[SAMPLE_NUM_][SUBSET_]; };

__device__ __forceinline__ unsigned smem_u32(const void* p) {
    unsigned a;
    asm("{ .reg .u64 t; cvta.to.shared.u64 t, %1; cvt.u32.u64 %0, t; }"
        : "=r"(a) : "l"(p));
    return a;
}

// ======================= Kernel A: cluster-parallel FPS =======================
// One 8-CTA cluster per batch. Slice in registers; REDUX warp argmax;
// DSMEM candidate exchange + one cluster barrier per iteration (parity slots).
// Exactly reproduces jnp.argmax first-index tie semantics.
__global__ __launch_bounds__(FPS_T_) __cluster_dims__(CLUSTER_, 1, 1)
void fps_cluster_kernel(const float* __restrict__ xyz)
{
    __shared__ float ox[SLICE_], oy[SLICE_], oz[SLICE_];
    __shared__ unsigned long long warr[FPS_T_ / 32];
    __shared__ unsigned long long skey[2][CLUSTER_];
    __shared__ float scx[2][CLUSTER_], scy[2][CLUSTER_], scz[2][CLUSTER_];

    const int t = threadIdx.x;
    unsigned rank;
    asm("mov.u32 %0, %%cluster_ctarank;" : "=r"(rank));
    const int b = blockIdx.x >> 3;
    const int base = (int)rank * SLICE_;
    const float* X = xyz + (size_t)b * N_ * 3;

    float px[PPT_], py[PPT_], pz[PPT_], dd[PPT_];
#pragma unroll
    for (int k = 0; k < PPT_; k++) {
        int l = (k << 8) + t;          // local index in slice
        int n = base + l;
        float x = X[n * 3 + 0], y = X[n * 3 + 1], z = X[n * 3 + 2];
        px[k] = x; py[k] = y; pz[k] = z;
        ox[l] = x; oy[l] = y; oz[l] = z;
        dd[k] = 1e10f;
        // pack for knn: (x,y,z,xx), xx reference-rounded
        float xx = __fadd_rn(__fadd_rn(__fmul_rn(x, x), __fmul_rn(y, y)),
                             __fmul_rn(z, z));
        g_pts[(size_t)b * N_ + n] = make_float4(x, y, z, xx);
    }
    __syncthreads();

    // initial centroid = point 0 (reference starts farthest=0)
    float cx = X[0], cy = X[1], cz = X[2];

    float* outc = g_centers + (size_t)b * NPOINT_ * 3;

    for (int s = 0; s < NPOINT_; s++) {
        if (rank == 0 && t == 0) {
            outc[s * 3 + 0] = cx; outc[s * 3 + 1] = cy; outc[s * 3 + 2] = cz;
        }
        const int par = s & 1;

        // per-thread argmax (strict > keeps first index; n ascending in k)
        float maxd = -1.0f; int bi = 0;
#pragma unroll
        for (int k = 0; k < PPT_; k++) {
            int n = base + (k << 8) + t;
            // match XLA: ((dx*dx + dy*dy) + dz*dz), each op rounded, no FMA
            float dx = __fsub_rn(px[k], cx);
            float dy = __fsub_rn(py[k], cy);
            float dz = __fsub_rn(pz[k], cz);
            float d  = __fadd_rn(__fadd_rn(__fmul_rn(dx, dx), __fmul_rn(dy, dy)),
                                 __fmul_rn(dz, dz));
            float nd = fminf(dd[k], d);
            dd[k] = nd;
            if (nd > maxd) { maxd = nd; bi = n; }
        }
        // warp argmax via REDUX: dist bits (>=0, monotone), then ~idx among matches
        unsigned hb = __float_as_uint(maxd);
        unsigned mh = __reduce_max_sync(0xffffffffu, hb);
        unsigned cd = (hb == mh) ? ~(unsigned)bi : 0u;
        unsigned ml = __reduce_max_sync(0xffffffffu, cd);
        if ((t & 31) == 0)
            warr[t >> 5] = ((unsigned long long)mh << 32) | ml;
        __syncthreads();

        // all threads compute CTA-best (8 broadcast LDS)
        unsigned long long bb = warr[0];
#pragma unroll
        for (int w = 1; w < FPS_T_ / 32; w++) {
            unsigned long long v = warr[w];
            bb = (v > bb) ? v : bb;
        }

        // threads 0..7: send this CTA's candidate to cluster CTA t's slot[rank][par]
        if (t < CLUSTER_) {
            int g = (int)(~(unsigned)(bb & 0xffffffffu));
            int l = g - base;
            float wx = ox[l], wy = oy[l], wz = oz[l];
            unsigned a_key = smem_u32(&skey[par][rank]);
            unsigned a_cx  = smem_u32(&scx[par][rank]);
            unsigned a_cy  = smem_u32(&scy[par][rank]);
            unsigned a_cz  = smem_u32(&scz[par][rank]);
            unsigned r_key, r_cx, r_cy, r_cz;
            asm("mapa.shared::cluster.u32 %0, %1, %2;" : "=r"(r_key) : "r"(a_key), "r"(t));
            asm("mapa.shared::cluster.u32 %0, %1, %2;" : "=r"(r_cx)  : "r"(a_cx),  "r"(t));
            asm("mapa.shared::cluster.u32 %0, %1, %2;" : "=r"(r_cy)  : "r"(a_cy),  "r"(t));
            asm("mapa.shared::cluster.u32 %0, %1, %2;" : "=r"(r_cz)  : "r"(a_cz),  "r"(t));
            asm volatile("st.shared::cluster.b64 [%0], %1;" :: "r"(r_key), "l"(bb) : "memory");
            asm volatile("st.shared::cluster.b32 [%0], %1;" :: "r"(r_cx), "r"(__float_as_uint(wx)) : "memory");
            asm volatile("st.shared::cluster.b32 [%0], %1;" :: "r"(r_cy), "r"(__float_as_uint(wy)) : "memory");
            asm volatile("st.shared::cluster.b32 [%0], %1;" :: "r"(r_cz), "r"(__float_as_uint(wz)) : "memory");
        }

        // one cluster barrier per iteration (release orders the DSMEM stores)
        asm volatile("barrier.cluster.arrive.aligned;" ::: "memory");
        asm volatile("barrier.cluster.wait.aligned;" ::: "memory");

        // winner among the 8 slots (broadcast LDS; parity protects slot reuse)
        unsigned long long w0 = skey[par][0];
        int wi = 0;
#pragma unroll
        for (int r = 1; r < CLUSTER_; r++) {
            unsigned long long v = skey[par][r];
            if (v > w0) { w0 = v; wi = r; }
        }
        cx = scx[par][wi]; cy = scy[par][wi]; cz = scz[par][wi];
    }
}

// ======================= Kernel B: KNN + robust centroid + features =======================
// One block per center. Per-thread exact sorted top-4 -> 256-way merge by
// warp 0 (REDUX min, no block barriers in the loop). Rare exact refill.
__global__ __launch_bounds__(256, 4) void knn_feat_kernel(float* __restrict__ out,
                                                          Perms perms)
{
    __shared__ unsigned long long cand_s[256 * 4];
    __shared__ unsigned long long heads_s[256];
    __shared__ unsigned char curs[256];
    __shared__ int nb[K_];
    __shared__ float gx[K_], gy[K_], gz[K_];
    __shared__ float cdx[SAMPLE_NUM_], cdy[SAMPLE_NUM_], cdz[SAMPLE_NUM_];

    const int bs = blockIdx.x;           // b * NPOINT + s
    const int b = bs >> 10;
    const int t = threadIdx.x;
    const float4* P = g_pts + (size_t)b * N_;

    const float cx = g_centers[bs * 3 + 0];
    const float cy = g_centers[bs * 3 + 1];
    const float cz = g_centers[bs * 3 + 2];
    const float cc = __fadd_rn(__fadd_rn(__fmul_rn(cx, cx), __fmul_rn(cy, cy)),
                               __fmul_rn(cz, cz));

    // exact sorted top-4 per thread (strict < keeps first index on ties;
    // n ascending within thread; d2 never -0.0 under RN)
    float v0 = FLT_MAX, v1 = FLT_MAX, v2 = FLT_MAX, v3 = FLT_MAX;
    int i0 = 0, i1 = 0, i2 = 0, i3 = 0;
#pragma unroll 8
    for (int k = 0; k < 64; k++) {
        int n = t + (k << 8);
        float4 p = __ldg(&P[n]);
        float dt = __fadd_rn(__fadd_rn(__fmul_rn(cx, p.x), __fmul_rn(cy, p.y)),
                             __fmul_rn(cz, p.z));
        // match reference: (cc + xx) - 2*dot
        float d2 = __fsub_rn(__fadd_rn(cc, p.w), __fmul_rn(2.0f, dt));
        if (d2 < v3) {
            if (d2 < v2) {
                v3 = v2; i3 = i2;
                if (d2 < v1) {
                    v2 = v1; i2 = i1;
                    if (d2 < v0) { v1 = v0; i1 = i0; v0 = d2; i0 = n; }
                    else         { v1 = d2; i1 = n; }
                } else { v2 = d2; i2 = n; }
            } else { v3 = d2; i3 = n; }
        }
    }
    auto pack = [](float v, int n) -> unsigned long long {
        unsigned fb = __float_as_uint(v);
        fb = (fb & 0x80000000u) ? ~fb : (fb | 0x80000000u);   // monotone map
        return ((unsigned long long)fb << 32) | (unsigned)n;
    };
    cand_s[t * 4 + 0] = pack(v0, i0);
    cand_s[t * 4 + 1] = pack(v1, i1);
    cand_s[t * 4 + 2] = pack(v2, i2);
    cand_s[t * 4 + 3] = pack(v3, i3);
    heads_s[t] = cand_s[t * 4 + 0];
    curs[t] = 0;
    __syncthreads();

    // ---- warp 0: 32-round 256-way merge (ascending d2, ties -> lower index) ----
    if (t < 32) {
        const int baseT = t * 8;
        for (int j = 0; j < K_; j++) {
            unsigned long long lm = heads_s[baseT]; int li = 0;
#pragma unroll
            for (int i = 1; i < 8; i++) {
                unsigned long long v = heads_s[baseT + i];
                if (v < lm) { lm = v; li = i; }
            }
            unsigned hi = (unsigned)(lm >> 32), lo = (unsigned)lm;
            unsigned mh = __reduce_min_sync(0xffffffffu, hi);
            unsigned cl = (hi == mh) ? lo : 0xffffffffu;
            unsigned ml = __reduce_min_sync(0xffffffffu, cl);
            unsigned long long w = ((unsigned long long)mh << 32) | ml;
            if (t == 0) nb[j] = (int)ml;
            if (lm == w) {                       // unique owner lane
                int T = baseT + li;
                int c = (int)curs[T] + 1;
                curs[T] = (unsigned char)c;
                unsigned long long nh;
                if (c < 4) {
                    nh = cand_s[T * 4 + c];
                } else {
                    // exact refill: min key > w over T's 64 points (rare)
                    nh = 0xFFFFFFFFFFFFFFFFull;
                    for (int k = 0; k < 64; k++) {
                        int n = T + (k << 8);
                        float4 p = __ldg(&P[n]);
                        float dt = __fadd_rn(__fadd_rn(__fmul_rn(cx, p.x), __fmul_rn(cy, p.y)),
                                             __fmul_rn(cz, p.z));
                        float d2 = __fsub_rn(__fadd_rn(cc, p.w), __fmul_rn(2.0f, dt));
                        unsigned fb = __float_as_uint(d2);
                        fb = (fb & 0x80000000u) ? ~fb : (fb | 0x80000000u);
                        unsigned long long pk = ((unsigned long long)fb << 32) | (unsigned)n;
                        if (pk > w && pk < nh) nh = pk;
                    }
                }
                heads_s[T] = nh;
            }
        }
    }
    __syncthreads();

    // ---- gather the 32 neighbors (in selection order) ----
    if (t < K_) {
        int n = nb[t];
        float4 p = P[n];
        gx[t] = p.x; gy[t] = p.y; gz[t] = p.z;
    }
    __syncthreads();

    // ---- 10 candidate centroids: mean over fixed 29-element permutation subsets ----
    if (t < SAMPLE_NUM_) {
        float ax = 0.f, ay = 0.f, az = 0.f;
        for (int j = 0; j < SUBSET_; j++) {
            int p = perms.p[t][j];
            ax += gx[p]; ay += gy[p]; az += gz[p];
        }
        cdx[t] = ax / (float)SUBSET_;
        cdy[t] = ay / (float)SUBSET_;
        cdz[t] = az / (float)SUBSET_;
    }
    __syncthreads();

    // ---- candidate selection (7 most central of 10) + features ----
    if (t == 0) {
        float sq[SAMPLE_NUM_], ps[SAMPLE_NUM_];
        for (int j = 0; j < SAMPLE_NUM_; j++)
            sq[j] = cdx[j] * cdx[j] + cdy[j] * cdy[j] + cdz[j] * cdz[j];
        for (int j = 0; j < SAMPLE_NUM_; j++) {
            float acc = 0.f;
            for (int k2 = 0; k2 < SAMPLE_NUM_; k2++) {
                float dt = cdx[j] * cdx[k2] + cdy[j] * cdy[k2] + cdz[j] * cdz[k2];
                acc += sq[j] + sq[k2] - 2.0f * dt;
            }
            ps[j] = acc;
        }
        bool used[SAMPLE_NUM_];
        for (int j = 0; j < SAMPLE_NUM_; j++) used[j] = false;
        float mx = 0.f, my = 0.f, mz = 0.f;
        for (int r = 0; r < SEL_; r++) {
            int bsel = 0; float bv = FLT_MAX;
            for (int k2 = 0; k2 < SAMPLE_NUM_; k2++)
                if (!used[k2] && ps[k2] < bv) { bv = ps[k2]; bsel = k2; }
            used[bsel] = true;
            mx += cdx[bsel]; my += cdy[bsel]; mz += cdz[bsel];
        }
        mx /= (float)SEL_; my /= (float)SEL_; mz /= (float)SEL_;

        float ref_norm = sqrtf(cx * cx + cy * cy + cz * cz);
        float den = ref_norm + 1e-4f;
        float ux = cx / den, uy = cy / den, uz = cz / den;
        float ix = RADIUS_ * ux + cx, iy = RADIUS_ * uy + cy, iz = RADIUS_ * uz + cz;

        float crx = cx - mx, cry = cy - my, crz = cz - mz;
        float crd = sqrtf(crx * crx + cry * cry + crz * crz);
        float cvx = ix - mx, cvy = iy - my, cvz = iz - mz;
        float cid = sqrtf(cvx * cvx + cvy * cvy + cvz * cvz);
        float dot = crx * cvx + cry * cvy + crz * cvz;
        float ang_rci = dot / (crd * cid + 1e-6f);

        float irx = cx - ix, iry = cy - iy, irz = cz - iz;
        float icx = mx - ix, icy = my - iy, icz = mz - iz;
        float dot2 = irx * icx + iry * icy + irz * icz;
        float ang_ric = dot2 / (RADIUS_ * cid + 1e-6f);

        float* o = out + (size_t)bs * 5;
        o[0] = ref_norm; o[1] = crd; o[2] = cid; o[3] = ang_rci; o[4] = ang_ric;
    }
}

// ======================= Host: threefry-2x32 (JAX partitionable PRNG) =======================
static inline uint32_t rotl32_(uint32_t x, int r) { return (x << r) | (x >> (32 - r)); }

static void tf2x32_(uint32_t k0, uint32_t k1, uint32_t x0, uint32_t x1,
                    uint32_t& o0, uint32_t& o1)
{
    static const int R0[4] = {13, 15, 26, 6};
    static const int R1[4] = {17, 29, 16, 24};
    uint32_t ks[3] = {k0, k1, k0 ^ k1 ^ 0x1BD11BDAu};
    x0 += ks[0]; x1 += ks[1];
    for (int i = 0; i < 5; i++) {
        const int* R = (i & 1) ? R1 : R0;
        for (int j = 0; j < 4; j++) { x0 += x1; x1 = rotl32_(x1, R[j]); x1 ^= x0; }
        x0 += ks[(i + 1) % 3];
        x1 += ks[(i + 2) % 3] + (uint32_t)(i + 1);
    }
    o0 = x0; o1 = x1;
}

// jax.random.permutation(fold_in(key(42), i), 32)[:29], threefry partitionable mode.
static void make_perms(unsigned char p[SAMPLE_NUM_][SUBSET_])
{
    for (int i = 0; i < SAMPLE_NUM_; i++) {
        uint32_t k0, k1, s0, s1;
        tf2x32_(0u, 42u, 0u, (uint32_t)i, k0, k1);     // fold_in
        tf2x32_(k0, k1, 0u, 1u, s0, s1);               // split -> subkey (index 1)
        uint32_t bits[K_];
        for (int j = 0; j < K_; j++) {
            uint32_t hi, lo;
            tf2x32_(s0, s1, 0u, (uint32_t)j, hi, lo);
            bits[j] = hi ^ lo;                         // 32-bit path XORs both words
        }
        int idx[K_];
        for (int j = 0; j < K_; j++) idx[j] = j;
        for (int a = 1; a < K_; a++) {                 // stable insertion sort
            uint32_t bv = bits[a]; int iv = idx[a]; int c = a - 1;
            while (c >= 0 && bits[c] > bv) {
                bits[c + 1] = bits[c]; idx[c + 1] = idx[c]; c--;
            }
            bits[c + 1] = bv; idx[c + 1] = iv;
        }
        for (int j = 0; j < SUBSET_; j++) p[i][j] = (unsigned char)idx[j];
    }
}

extern "C" void kernel_launch(void* const* d_in, const int* in_sizes, int n_in,
                              void* d_out, int out_size)
{
    (void)in_sizes; (void)n_in; (void)out_size;
    const float* xyz = (const float*)d_in[0];
    float* out = (float*)d_out;

    Perms perms;
    make_perms(perms.p);   // deterministic, cheap, every call

    fps_cluster_kernel<<<B_ * CLUSTER_, FPS_T_>>>(xyz);
    knn_feat_kernel<<<B_ * NPOINT_, 256>>>(out, perms);
}